// round 8
// baseline (speedup 1.0000x reference)
#include <cuda_runtime.h>
#include <cuda_bf16.h>
#include <cstdint>

// ---------------------------------------------------------------------------
// SNN on B200 (compute_100 => mma.sync tf32, 3-term split, SMEM sum tile)
//
//   K1: cur = x @ W1^T (128x128 tile) via 3xTF32 split mma.sync, 512 threads,
//       TC acc drained every 2 K-tiles into an SMEM fp32 sum tile S,
//       fused epilogue: LIF mem1 recurrence over t from S, spikes -> g_spk.
//   K2: cur2[m, o] = spk[m, :] @ W2[o, :]   (warp per row, exact products)
//   K3: mem2 leaky integration
// ---------------------------------------------------------------------------

#define BATCH   256
#define T_STEPS 128
#define K_IN    1156
#define N_HID   1024
#define N_OUT   10
#define M_TOTAL (BATCH * T_STEPS)   // 32768
#define KTILES  37                  // ceil(1156/32)
#define SA      36                  // stage row stride (floats)
#define SC      132                 // sum-tile row stride (floats)

__device__ __nv_bfloat16 g_spk[(size_t)M_TOTAL * N_HID];   // 64 MB
__device__ float         g_cur2[(size_t)M_TOTAL * N_OUT];  // 1.3 MB

// ===================== helpers =============================================
__device__ __forceinline__ uint32_t smem_u32(const void* p) {
    uint32_t a;
    asm("{ .reg .u64 t; cvta.to.shared.u64 t, %1; cvt.u32.u64 %0, t; }"
        : "=r"(a) : "l"(p));
    return a;
}

__device__ __forceinline__ void cp_async16(uint32_t dst, const void* src, int bytes) {
    asm volatile("cp.async.cg.shared.global [%0], [%1], 16, %2;"
                 :: "r"(dst), "l"(src), "r"(bytes));
}
#define CP_COMMIT() asm volatile("cp.async.commit_group;" ::: "memory")
#define CP_WAIT1()  asm volatile("cp.async.wait_group 1;" ::: "memory")

__device__ __forceinline__ void split1(float v, uint32_t& hi, uint32_t& lo) {
    asm("cvt.rna.tf32.f32 %0, %1;" : "=r"(hi) : "f"(v));
    float l = v - __uint_as_float(hi);
    asm("cvt.rna.tf32.f32 %0, %1;" : "=r"(lo) : "f"(l));
}

__device__ __forceinline__ void mma8(float* c, const uint32_t* a, const uint32_t* b) {
    asm volatile(
        "mma.sync.aligned.m16n8k8.row.col.f32.tf32.tf32.f32 "
        "{%0,%1,%2,%3}, {%4,%5,%6,%7}, {%8,%9}, {%0,%1,%2,%3};"
        : "+f"(c[0]), "+f"(c[1]), "+f"(c[2]), "+f"(c[3])
        : "r"(a[0]), "r"(a[1]), "r"(a[2]), "r"(a[3]), "r"(b[0]), "r"(b[1]));
}

// ===================== K1: GEMM + fused spike scan =========================
// SMEM (floats): stage0[9216] stage1[9216] S[128*132=16896] -> 141312 bytes
#define STAGE_FLOATS (2 * 128 * SA)              // 9216
#define S_OFF        (2 * STAGE_FLOATS)          // 18432
#define GEMM_SMEM    ((S_OFF + 128 * SC) * 4)    // 141312 B

__global__ __launch_bounds__(512, 1)
void snn_gemm_spike(const float* __restrict__ A,   // x  [M_TOTAL, K_IN]
                    const float* __restrict__ B)   // W1 [N_HID,  K_IN]
{
    extern __shared__ float sm[];
    const uint32_t sbase = smem_u32(sm);
    float* S = sm + S_OFF;

    const int tid  = threadIdx.x;          // 512 threads, 16 warps
    const int wid  = tid >> 5;
    const int lane = tid & 31;
    const int wm   = wid >> 2;             // 0..3 -> 32 rows each
    const int wn   = wid & 3;              // 0..3 -> 32 cols each
    const int b    = blockIdx.y;           // one batch element = 128 rows
    const int n0   = blockIdx.x * 128;

    const float* Abase = A + (size_t)b * 128 * K_IN;
    const float* Bbase = B + (size_t)n0 * K_IN;

    // zero sum tile
    for (int i = tid; i < 128 * SC; i += 512) S[i] = 0.f;

    auto prefetch = [&](int it) {
        const int s  = it & 1;
        const int kb = it * 32;
        const uint32_t sA = sbase + (uint32_t)s * STAGE_FLOATS * 4;
        const uint32_t sB = sA + 128 * SA * 4;
#pragma unroll
        for (int i = 0; i < 2; ++i) {
            const int f   = tid + i * 512;   // 0..1023
            const int row = f >> 3;
            const int j   = f & 7;
            const int k0  = kb + j * 4;
            int rem = K_IN - k0;
            int bytes = rem <= 0 ? 0 : (rem >= 4 ? 16 : rem * 4);
            const int ksafe = (k0 < K_IN) ? k0 : 0;
            const uint32_t off = (uint32_t)(row * SA + j * 4) * 4;
            cp_async16(sA + off, Abase + (size_t)row * K_IN + ksafe, bytes);
            cp_async16(sB + off, Bbase + (size_t)row * K_IN + ksafe, bytes);
        }
    };

    prefetch(0);
    CP_COMMIT();

    const int g  = lane >> 2;   // 0..7
    const int tg = lane & 3;    // 0..3

    float acc[2][4][4];         // warp tile 32x32: 2 m16 x 4 n8

    for (int it = 0; it < KTILES; ++it) {
        if (it + 1 < KTILES) prefetch(it + 1);
        CP_COMMIT();
        CP_WAIT1();
        __syncthreads();

        if ((it & 1) == 0) {    // fresh TC accumulator every 2 K-tiles
#pragma unroll
            for (int i = 0; i < 2; i++)
#pragma unroll
                for (int j = 0; j < 4; j++)
#pragma unroll
                    for (int q = 0; q < 4; q++) acc[i][j][q] = 0.f;
        }

        const int s = it & 1;
        const float* As = sm + s * STAGE_FLOATS;
        const float* Bs = As + 128 * SA;

#pragma unroll
        for (int ks = 0; ks < 4; ++ks) {
            uint32_t ahi[2][4], alo[2][4], bhi[4][2], blo[4][2];
#pragma unroll
            for (int mi = 0; mi < 2; ++mi) {
                const int r = wm * 32 + mi * 16 + g;
                const int c = ks * 8 + tg;
                split1(As[r * SA + c],           ahi[mi][0], alo[mi][0]);
                split1(As[(r + 8) * SA + c],     ahi[mi][1], alo[mi][1]);
                split1(As[r * SA + c + 4],       ahi[mi][2], alo[mi][2]);
                split1(As[(r + 8) * SA + c + 4], ahi[mi][3], alo[mi][3]);
            }
#pragma unroll
            for (int ni = 0; ni < 4; ++ni) {
                const int n = wn * 32 + ni * 8 + g;
                const int k = ks * 8 + tg;
                split1(Bs[n * SA + k],     bhi[ni][0], blo[ni][0]);
                split1(Bs[n * SA + k + 4], bhi[ni][1], blo[ni][1]);
            }
#pragma unroll
            for (int mi = 0; mi < 2; ++mi)
#pragma unroll
                for (int ni = 0; ni < 4; ++ni) {
                    mma8(acc[mi][ni], ahi[mi], bhi[ni]);
                    mma8(acc[mi][ni], ahi[mi], blo[ni]);
                    mma8(acc[mi][ni], alo[mi], bhi[ni]);
                }
        }

        // drain into SMEM sum tile every 2 tiles (and on the last tile)
        if ((it & 1) == 1 || it == KTILES - 1) {
#pragma unroll
            for (int mi = 0; mi < 2; ++mi)
#pragma unroll
                for (int ni = 0; ni < 4; ++ni) {
                    const int r = wm * 32 + mi * 16 + g;
                    const int c = wn * 32 + ni * 8 + tg * 2;
                    S[r * SC + c]           += acc[mi][ni][0];
                    S[r * SC + c + 1]       += acc[mi][ni][1];
                    S[(r + 8) * SC + c]     += acc[mi][ni][2];
                    S[(r + 8) * SC + c + 1] += acc[mi][ni][3];
                }
        }
        __syncthreads();
    }

    // ---- epilogue: LIF scan over t directly from S ----
    if (tid < 128) {
        float mem1 = 0.f;
        __nv_bfloat16* dst = g_spk + (size_t)b * 128 * N_HID + n0 + tid;
        float c = S[tid];   // t = 0
#pragma unroll 4
        for (int t = 0; t < T_STEPS; ++t) {
            float cn = (t + 1 < T_STEPS) ? S[(t + 1) * SC + tid] : 0.f;
            const float reset = (mem1 > 1.0f) ? 1.0f : 0.0f;
            mem1 = 0.95f * mem1 + c - reset;
            dst[(size_t)t * N_HID] = __float2bfloat16((mem1 > 1.0f) ? 1.0f : 0.0f);
            c = cn;
        }
    }
}

// ===================== K2: cur2 = spk @ W2^T ================================
__global__ __launch_bounds__(256)
void snn_gemm2(const float* __restrict__ W2)   // [N_OUT, N_HID]
{
    __shared__ float w2s[N_HID * 11];
    const int tid  = threadIdx.x;
    const int wid  = tid >> 5;
    const int lane = tid & 31;

    for (int i = tid; i < N_HID * N_OUT; i += 256) {
        const int h = i / N_OUT;
        const int o = i - h * N_OUT;
        w2s[h * 11 + o] = W2[o * N_HID + h];
    }
    __syncthreads();

    const size_t m = (size_t)blockIdx.x * 8 + wid;
    const __nv_bfloat16* srow = g_spk + m * N_HID;

    float acc[N_OUT];
#pragma unroll
    for (int o = 0; o < N_OUT; o++) acc[o] = 0.f;

#pragma unroll 4
    for (int j = 0; j < 32; ++j) {
        const int h = lane + j * 32;
        const float s = __bfloat162float(srow[h]);
        if (s != 0.f) {
#pragma unroll
            for (int o = 0; o < N_OUT; o++) acc[o] += w2s[h * 11 + o];
        }
    }

#pragma unroll
    for (int o = 0; o < N_OUT; o++) {
        acc[o] += __shfl_down_sync(0xffffffffu, acc[o], 16);
        acc[o] += __shfl_down_sync(0xffffffffu, acc[o], 8);
        acc[o] += __shfl_down_sync(0xffffffffu, acc[o], 4);
        acc[o] += __shfl_down_sync(0xffffffffu, acc[o], 2);
        acc[o] += __shfl_down_sync(0xffffffffu, acc[o], 1);
    }
    if (lane == 0) {
#pragma unroll
        for (int o = 0; o < N_OUT; o++) g_cur2[m * N_OUT + o] = acc[o];
    }
}

// ===================== K3: mem2 leaky integration ==========================
__global__ void snn_scan2(float* __restrict__ out)   // [T, B, N_OUT]
{
    const int id = blockIdx.x * 256 + threadIdx.x;
    if (id >= BATCH * N_OUT) return;
    const int bb = id / N_OUT;
    const int o  = id - bb * N_OUT;

    float m2 = 0.f;
    for (int t = 0; t < T_STEPS; ++t) {
        m2 = 0.95f * m2 + g_cur2[((size_t)bb * T_STEPS + t) * N_OUT + o];
        out[((size_t)t * BATCH + bb) * N_OUT + o] = m2;
    }
}

// ===================== launch ==============================================
extern "C" void kernel_launch(void* const* d_in, const int* in_sizes, int n_in,
                              void* d_out, int out_size)
{
    const float* x  = (const float*)d_in[0];   // [B, T, K_IN]
    const float* W1 = (const float*)d_in[1];   // [N_HID, K_IN]
    const float* W2 = (const float*)d_in[2];   // [N_OUT, N_HID]
    float* out = (float*)d_out;                // [T, B, N_OUT]

    cudaFuncSetAttribute(snn_gemm_spike,
                         cudaFuncAttributeMaxDynamicSharedMemorySize, GEMM_SMEM);

    dim3 grid1(N_HID / 128, M_TOTAL / 128);    // (8, 256)
    snn_gemm_spike<<<grid1, 512, GEMM_SMEM>>>(x, W1);
    snn_gemm2<<<M_TOTAL / 8, 256>>>(W2);
    snn_scan2<<<(BATCH * N_OUT + 255) / 256, 256>>>(out);
}

// round 9
// speedup vs baseline: 1.0493x; 1.0493x over previous
#include <cuda_runtime.h>
#include <cuda_bf16.h>
#include <cstdint>

// ---------------------------------------------------------------------------
// SNN on B200 (compute_100 => mma.sync tf32, 3-term split)
//
//   P:  prepass splits x and W1 into global interleaved (hi,lo) tf32 pairs,
//       zero-padded to K_PAD=1184 (no bounds checks downstream).
//   K1: cur = x @ W1^T (128x128 tile): mainloop is pure LDS.v2 + mma.sync
//       (hi*hi + hi*lo + lo*hi), per-K-tile TC acc drained to register sums,
//       fused epilogue: LIF mem1 recurrence, spikes (bf16) -> g_spk.
//   K2: cur2 = spk @ W2^T (warp per row, exact products)
//   K3: mem2 leaky integration
// ---------------------------------------------------------------------------

#define BATCH   256
#define T_STEPS 128
#define K_IN    1156
#define N_HID   1024
#define N_OUT   10
#define M_TOTAL (BATCH * T_STEPS)   // 32768
#define KTILES  37
#define K_PAD   (KTILES * 32)       // 1184
#define SROW    72                  // stage row stride in floats (32 k * 2 + pad 8)

__device__ float         g_xs[(size_t)M_TOTAL * K_PAD * 2];  // 310 MB
__device__ float         g_ws[(size_t)N_HID  * K_PAD * 2];   // 9.7 MB
__device__ __nv_bfloat16 g_spk[(size_t)M_TOTAL * N_HID];     // 64 MB
__device__ float         g_cur2[(size_t)M_TOTAL * N_OUT];    // 1.3 MB

// ===================== helpers =============================================
__device__ __forceinline__ uint32_t smem_u32(const void* p) {
    uint32_t a;
    asm("{ .reg .u64 t; cvta.to.shared.u64 t, %1; cvt.u32.u64 %0, t; }"
        : "=r"(a) : "l"(p));
    return a;
}
__device__ __forceinline__ void cp_async16(uint32_t dst, const void* src) {
    asm volatile("cp.async.cg.shared.global [%0], [%1], 16;"
                 :: "r"(dst), "l"(src));
}
#define CP_COMMIT() asm volatile("cp.async.commit_group;" ::: "memory")
#define CP_WAIT1()  asm volatile("cp.async.wait_group 1;" ::: "memory")

__device__ __forceinline__ void split1f(float v, float& hi, float& lo) {
    uint32_t h;
    asm("cvt.rna.tf32.f32 %0, %1;" : "=r"(h) : "f"(v));
    hi = __uint_as_float(h);
    float l = v - hi;
    uint32_t l2;
    asm("cvt.rna.tf32.f32 %0, %1;" : "=r"(l2) : "f"(l));
    lo = __uint_as_float(l2);
}

__device__ __forceinline__ void mma8(float* c, const uint32_t* a, const uint32_t* b) {
    asm volatile(
        "mma.sync.aligned.m16n8k8.row.col.f32.tf32.tf32.f32 "
        "{%0,%1,%2,%3}, {%4,%5,%6,%7}, {%8,%9}, {%0,%1,%2,%3};"
        : "+f"(c[0]), "+f"(c[1]), "+f"(c[2]), "+f"(c[3])
        : "r"(a[0]), "r"(a[1]), "r"(a[2]), "r"(a[3]), "r"(b[0]), "r"(b[1]));
}

// ===================== P: split prepass ====================================
// src [rows, K_IN] -> dst [rows, K_PAD, 2] interleaved (hi, lo), zero-padded.
__global__ __launch_bounds__(256)
void split_prepass(const float* __restrict__ src, float* __restrict__ dst, int rows)
{
    const size_t idx = (size_t)blockIdx.x * 256 + threadIdx.x;  // float4 chunk id
    const size_t nchunk = (size_t)rows * (K_PAD / 4);
    if (idx >= nchunk) return;
    const int row = (int)(idx / (K_PAD / 4));
    const int k0  = (int)(idx % (K_PAD / 4)) * 4;

    float4 v = make_float4(0.f, 0.f, 0.f, 0.f);
    if (k0 < K_IN)   // K_IN % 4 == 0: chunks are fully valid or fully pad
        v = *(const float4*)(src + (size_t)row * K_IN + k0);

    float hx, lx, hy, ly, hz, lz, hw, lw;
    split1f(v.x, hx, lx); split1f(v.y, hy, ly);
    split1f(v.z, hz, lz); split1f(v.w, hw, lw);

    float* d = dst + ((size_t)row * K_PAD + k0) * 2;
    *(float4*)(d)     = make_float4(hx, lx, hy, ly);
    *(float4*)(d + 4) = make_float4(hz, lz, hw, lw);
}

// ===================== K1: GEMM + fused spike scan =========================
// SMEM: stage = A[128*SROW] + B[128*SROW] floats; double-buffered.
#define STAGE_FLOATS (2 * 128 * SROW)            // 18432
#define GEMM_SMEM    (2 * STAGE_FLOATS * 4)      // 147456 B (epilogue cur fits)

__global__ __launch_bounds__(256, 1)
void snn_gemm_spike()
{
    extern __shared__ float sm[];
    const uint32_t sbase = smem_u32(sm);
    const int tid  = threadIdx.x;          // 256 threads, 8 warps
    const int wid  = tid >> 5;
    const int lane = tid & 31;
    const int wm   = wid >> 2;             // 0..1 -> 64 rows
    const int wn   = wid & 3;              // 0..3 -> 32 cols
    const int b    = blockIdx.y;           // one batch element = 128 rows
    const int n0   = blockIdx.x * 128;

    const float* Abase = g_xs + (size_t)b * 128 * K_PAD * 2;
    const float* Bbase = g_ws + (size_t)n0 * K_PAD * 2;

    float sum[4][4][4];
#pragma unroll
    for (int i = 0; i < 4; i++)
#pragma unroll
        for (int j = 0; j < 4; j++)
#pragma unroll
            for (int q = 0; q < 4; q++) sum[i][j][q] = 0.f;

    // loader: per stage, per operand: 128 rows x 16 float4 = 2048 chunks
    auto prefetch = [&](int it) {
        const int s  = it & 1;
        const size_t kb2 = (size_t)it * 64;   // k-tile offset in floats (32k * 2)
        const uint32_t sA = sbase + (uint32_t)s * STAGE_FLOATS * 4;
        const uint32_t sB = sA + 128 * SROW * 4;
#pragma unroll
        for (int i = 0; i < 8; ++i) {
            const int f   = tid + i * 256;    // 0..2047
            const int row = f >> 4;
            const int j   = f & 15;
            const uint32_t off = (uint32_t)(row * SROW + j * 4) * 4;
            cp_async16(sA + off, Abase + (size_t)row * K_PAD * 2 + kb2 + j * 4);
            cp_async16(sB + off, Bbase + (size_t)row * K_PAD * 2 + kb2 + j * 4);
        }
    };

    prefetch(0);
    CP_COMMIT();

    const int g  = lane >> 2;   // 0..7
    const int tg = lane & 3;    // 0..3

    for (int it = 0; it < KTILES; ++it) {
        if (it + 1 < KTILES) prefetch(it + 1);
        CP_COMMIT();
        CP_WAIT1();
        __syncthreads();

        const int s = it & 1;
        const float2* As2 = (const float2*)(sm + s * STAGE_FLOATS);
        const float2* Bs2 = As2 + 128 * (SROW / 2);

        float acc[4][4][4];   // per-K-tile TC accumulator
#pragma unroll
        for (int i = 0; i < 4; i++)
#pragma unroll
            for (int j = 0; j < 4; j++)
#pragma unroll
                for (int q = 0; q < 4; q++) acc[i][j][q] = 0.f;

#pragma unroll
        for (int ks = 0; ks < 4; ++ks) {
            uint32_t ahi[4][4], alo[4][4], bhi[4][2], blo[4][2];
            const int c = ks * 8 + tg;
#pragma unroll
            for (int mi = 0; mi < 4; ++mi) {
                const int r = wm * 64 + mi * 16 + g;
                float2 p0 = As2[r * (SROW / 2) + c];
                float2 p1 = As2[(r + 8) * (SROW / 2) + c];
                float2 p2 = As2[r * (SROW / 2) + c + 4];
                float2 p3 = As2[(r + 8) * (SROW / 2) + c + 4];
                ahi[mi][0] = __float_as_uint(p0.x); alo[mi][0] = __float_as_uint(p0.y);
                ahi[mi][1] = __float_as_uint(p1.x); alo[mi][1] = __float_as_uint(p1.y);
                ahi[mi][2] = __float_as_uint(p2.x); alo[mi][2] = __float_as_uint(p2.y);
                ahi[mi][3] = __float_as_uint(p3.x); alo[mi][3] = __float_as_uint(p3.y);
            }
#pragma unroll
            for (int ni = 0; ni < 4; ++ni) {
                const int n = wn * 32 + ni * 8 + g;
                float2 q0 = Bs2[n * (SROW / 2) + c];
                float2 q1 = Bs2[n * (SROW / 2) + c + 4];
                bhi[ni][0] = __float_as_uint(q0.x); blo[ni][0] = __float_as_uint(q0.y);
                bhi[ni][1] = __float_as_uint(q1.x); blo[ni][1] = __float_as_uint(q1.y);
            }
#pragma unroll
            for (int mi = 0; mi < 4; ++mi)
#pragma unroll
                for (int ni = 0; ni < 4; ++ni) {
                    mma8(acc[mi][ni], ahi[mi], bhi[ni]);
                    mma8(acc[mi][ni], ahi[mi], blo[ni]);
                    mma8(acc[mi][ni], alo[mi], bhi[ni]);
                }
        }

#pragma unroll
        for (int mi = 0; mi < 4; ++mi)
#pragma unroll
            for (int ni = 0; ni < 4; ++ni)
#pragma unroll
                for (int q = 0; q < 4; ++q)
                    sum[mi][ni][q] += acc[mi][ni][q];

        __syncthreads();
    }

    // ---- epilogue: sums -> SMEM cur tile [128 t][132], LIF scan ----
    float* cur = sm;   // 128*132*4 = 67584 <= 147456
#pragma unroll
    for (int mi = 0; mi < 4; ++mi)
#pragma unroll
        for (int ni = 0; ni < 4; ++ni) {
            const int r = wm * 64 + mi * 16 + g;
            const int c = wn * 32 + ni * 8 + tg * 2;
            cur[r * 132 + c]           = sum[mi][ni][0];
            cur[r * 132 + c + 1]       = sum[mi][ni][1];
            cur[(r + 8) * 132 + c]     = sum[mi][ni][2];
            cur[(r + 8) * 132 + c + 1] = sum[mi][ni][3];
        }
    __syncthreads();

    if (tid < 128) {
        float mem1 = 0.f;
        __nv_bfloat16* dst = g_spk + (size_t)b * 128 * N_HID + n0 + tid;
        float c = cur[tid];
#pragma unroll 4
        for (int t = 0; t < T_STEPS; ++t) {
            float cn = (t + 1 < T_STEPS) ? cur[(t + 1) * 132 + tid] : 0.f;
            const float reset = (mem1 > 1.0f) ? 1.0f : 0.0f;
            mem1 = 0.95f * mem1 + c - reset;
            dst[(size_t)t * N_HID] = __float2bfloat16((mem1 > 1.0f) ? 1.0f : 0.0f);
            c = cn;
        }
    }
}

// ===================== K2: cur2 = spk @ W2^T ================================
__global__ __launch_bounds__(256)
void snn_gemm2(const float* __restrict__ W2)   // [N_OUT, N_HID]
{
    __shared__ float w2s[N_HID * 11];
    const int tid  = threadIdx.x;
    const int wid  = tid >> 5;
    const int lane = tid & 31;

    for (int i = tid; i < N_HID * N_OUT; i += 256) {
        const int h = i / N_OUT;
        const int o = i - h * N_OUT;
        w2s[h * 11 + o] = W2[o * N_HID + h];
    }
    __syncthreads();

    const size_t m = (size_t)blockIdx.x * 8 + wid;
    const __nv_bfloat16* srow = g_spk + m * N_HID;

    float acc[N_OUT];
#pragma unroll
    for (int o = 0; o < N_OUT; o++) acc[o] = 0.f;

#pragma unroll 4
    for (int j = 0; j < 32; ++j) {
        const int h = lane + j * 32;
        const float s = __bfloat162float(srow[h]);
        if (s != 0.f) {
#pragma unroll
            for (int o = 0; o < N_OUT; o++) acc[o] += w2s[h * 11 + o];
        }
    }

#pragma unroll
    for (int o = 0; o < N_OUT; o++) {
        acc[o] += __shfl_down_sync(0xffffffffu, acc[o], 16);
        acc[o] += __shfl_down_sync(0xffffffffu, acc[o], 8);
        acc[o] += __shfl_down_sync(0xffffffffu, acc[o], 4);
        acc[o] += __shfl_down_sync(0xffffffffu, acc[o], 2);
        acc[o] += __shfl_down_sync(0xffffffffu, acc[o], 1);
    }
    if (lane == 0) {
#pragma unroll
        for (int o = 0; o < N_OUT; o++) g_cur2[m * N_OUT + o] = acc[o];
    }
}

// ===================== K3: mem2 leaky integration ==========================
__global__ void snn_scan2(float* __restrict__ out)   // [T, B, N_OUT]
{
    const int id = blockIdx.x * 256 + threadIdx.x;
    if (id >= BATCH * N_OUT) return;
    const int bb = id / N_OUT;
    const int o  = id - bb * N_OUT;

    float m2 = 0.f;
    for (int t = 0; t < T_STEPS; ++t) {
        m2 = 0.95f * m2 + g_cur2[((size_t)bb * T_STEPS + t) * N_OUT + o];
        out[((size_t)t * BATCH + bb) * N_OUT + o] = m2;
    }
}

// ===================== launch ==============================================
extern "C" void kernel_launch(void* const* d_in, const int* in_sizes, int n_in,
                              void* d_out, int out_size)
{
    const float* x  = (const float*)d_in[0];   // [B, T, K_IN]
    const float* W1 = (const float*)d_in[1];   // [N_HID, K_IN]
    const float* W2 = (const float*)d_in[2];   // [N_OUT, N_HID]
    float* out = (float*)d_out;                // [T, B, N_OUT]

    cudaFuncSetAttribute(snn_gemm_spike,
                         cudaFuncAttributeMaxDynamicSharedMemorySize, GEMM_SMEM);

    float* xs; float* ws;
    cudaGetSymbolAddress((void**)&xs, g_xs);
    cudaGetSymbolAddress((void**)&ws, g_ws);

    {   // prepass: split x and W1
        const size_t nx = (size_t)M_TOTAL * (K_PAD / 4);
        const size_t nw = (size_t)N_HID * (K_PAD / 4);
        split_prepass<<<(unsigned)((nx + 255) / 256), 256>>>(x, xs, M_TOTAL);
        split_prepass<<<(unsigned)((nw + 255) / 256), 256>>>(W1, ws, N_HID);
    }

    dim3 grid1(N_HID / 128, M_TOTAL / 128);    // (8, 256)
    snn_gemm_spike<<<grid1, 256, GEMM_SMEM>>>();
    snn_gemm2<<<M_TOTAL / 8, 256>>>(W2);
    snn_scan2<<<(BATCH * N_OUT + 255) / 256, 256>>>(out);
}

// round 10
// speedup vs baseline: 1.1901x; 1.1342x over previous
#include <cuda_runtime.h>
#include <cuda_bf16.h>
#include <cstdint>

// ---------------------------------------------------------------------------
// SNN on B200 (compute_100 => mma.sync tf32, 3-term split, PLANAR pre-split)
//
//   P:  prepass splits x and W1 into separate global hi / lo tf32 planes,
//       zero-padded to K_PAD=1184.
//   K1: cur = x @ W1^T (128x128 tile): mainloop = conflict-free LDS.32 + MMA
//       (hi*hi + hi*lo + lo*hi), per-K-tile TC acc drained to register sums.
//       Fused epilogue: LIF mem1 recurrence; spikes packed to a BITMASK
//       via __ballot_sync -> g_spkbits.
//   K2: cur2 = spk @ W2^T from bitmask (warp per row, __ffs over set bits)
//   K3: mem2 leaky integration
// ---------------------------------------------------------------------------

#define BATCH   256
#define T_STEPS 128
#define K_IN    1156
#define N_HID   1024
#define N_OUT   10
#define M_TOTAL (BATCH * T_STEPS)   // 32768
#define KTILES  37
#define K_PAD   (KTILES * 32)       // 1184
#define SA      36                  // plane row stride (floats)
#define PLANE   (128 * SA)          // 4608 floats per plane per stage

__device__ float    g_xs[(size_t)2 * M_TOTAL * K_PAD];   // hi plane, lo plane
__device__ float    g_ws[(size_t)2 * N_HID  * K_PAD];
__device__ uint32_t g_spkbits[(size_t)M_TOTAL * 32];     // 4 MB
__device__ float    g_cur2[(size_t)M_TOTAL * N_OUT];     // 1.3 MB

// ===================== helpers =============================================
__device__ __forceinline__ uint32_t smem_u32(const void* p) {
    uint32_t a;
    asm("{ .reg .u64 t; cvta.to.shared.u64 t, %1; cvt.u32.u64 %0, t; }"
        : "=r"(a) : "l"(p));
    return a;
}
__device__ __forceinline__ void cp_async16(uint32_t dst, const void* src) {
    asm volatile("cp.async.cg.shared.global [%0], [%1], 16;"
                 :: "r"(dst), "l"(src));
}
#define CP_COMMIT() asm volatile("cp.async.commit_group;" ::: "memory")
#define CP_WAIT1()  asm volatile("cp.async.wait_group 1;" ::: "memory")

__device__ __forceinline__ void split1f(float v, float& hi, float& lo) {
    uint32_t h;
    asm("cvt.rna.tf32.f32 %0, %1;" : "=r"(h) : "f"(v));
    hi = __uint_as_float(h);
    float l = v - hi;
    uint32_t l2;
    asm("cvt.rna.tf32.f32 %0, %1;" : "=r"(l2) : "f"(l));
    lo = __uint_as_float(l2);
}

__device__ __forceinline__ void mma8(float* c, const uint32_t* a, const uint32_t* b) {
    asm volatile(
        "mma.sync.aligned.m16n8k8.row.col.f32.tf32.tf32.f32 "
        "{%0,%1,%2,%3}, {%4,%5,%6,%7}, {%8,%9}, {%0,%1,%2,%3};"
        : "+f"(c[0]), "+f"(c[1]), "+f"(c[2]), "+f"(c[3])
        : "r"(a[0]), "r"(a[1]), "r"(a[2]), "r"(a[3]), "r"(b[0]), "r"(b[1]));
}

// ===================== P: planar split prepass =============================
__global__ __launch_bounds__(256)
void split_prepass(const float* __restrict__ src, float* __restrict__ dst_hi,
                   float* __restrict__ dst_lo, int rows)
{
    const size_t idx = (size_t)blockIdx.x * 256 + threadIdx.x;  // float4 chunk
    const size_t nchunk = (size_t)rows * (K_PAD / 4);
    if (idx >= nchunk) return;
    const int row = (int)(idx / (K_PAD / 4));
    const int k0  = (int)(idx % (K_PAD / 4)) * 4;

    float4 v = make_float4(0.f, 0.f, 0.f, 0.f);
    if (k0 < K_IN)   // K_IN % 4 == 0
        v = *(const float4*)(src + (size_t)row * K_IN + k0);

    float4 h, l;
    split1f(v.x, h.x, l.x); split1f(v.y, h.y, l.y);
    split1f(v.z, h.z, l.z); split1f(v.w, h.w, l.w);

    const size_t o = (size_t)row * K_PAD + k0;
    *(float4*)(dst_hi + o) = h;
    *(float4*)(dst_lo + o) = l;
}

// ===================== K1: GEMM + fused spike scan =========================
// SMEM stage: 4 planes (Ahi, Alo, Bhi, Blo) x 128 x SA floats; double buffer.
#define STAGE_FLOATS (4 * PLANE)                 // 18432
#define GEMM_SMEM    (2 * STAGE_FLOATS * 4)      // 147456 B

__global__ __launch_bounds__(256, 1)
void snn_gemm_spike()
{
    extern __shared__ float sm[];
    const uint32_t sbase = smem_u32(sm);
    const int tid  = threadIdx.x;          // 256 threads, 8 warps
    const int wid  = tid >> 5;
    const int lane = tid & 31;
    const int wm   = wid >> 2;             // 0..1 -> 64 rows
    const int wn   = wid & 3;              // 0..3 -> 32 cols
    const int b    = blockIdx.y;           // one batch element = 128 rows
    const int n0   = blockIdx.x * 128;

    const float* xs_hi = g_xs;
    const float* xs_lo = g_xs + (size_t)M_TOTAL * K_PAD;
    const float* ws_hi = g_ws;
    const float* ws_lo = g_ws + (size_t)N_HID * K_PAD;

    const size_t arow0 = (size_t)b * 128 * K_PAD;
    const size_t brow0 = (size_t)n0 * K_PAD;

    float sum[4][4][4];
#pragma unroll
    for (int i = 0; i < 4; i++)
#pragma unroll
        for (int j = 0; j < 4; j++)
#pragma unroll
            for (int q = 0; q < 4; q++) sum[i][j][q] = 0.f;

    // loader: 4 planes x 1024 float4-chunks; 256 threads x 16 chunks
    auto prefetch = [&](int it) {
        const int s  = it & 1;
        const int kb = it * 32;
        const uint32_t sst = sbase + (uint32_t)s * STAGE_FLOATS * 4;
#pragma unroll
        for (int q = 0; q < 16; ++q) {
            const int plane = q >> 2;                       // 0..3 (compile-time)
            const int f     = (q & 3) * 256 + tid;          // 0..1023
            const int row   = f >> 3;
            const int j     = f & 7;
            const uint32_t soff = (uint32_t)(plane * PLANE + row * SA + j * 4) * 4;
            const float* src;
            if (plane == 0)      src = xs_hi + arow0 + (size_t)row * K_PAD + kb + j * 4;
            else if (plane == 1) src = xs_lo + arow0 + (size_t)row * K_PAD + kb + j * 4;
            else if (plane == 2) src = ws_hi + brow0 + (size_t)row * K_PAD + kb + j * 4;
            else                 src = ws_lo + brow0 + (size_t)row * K_PAD + kb + j * 4;
            cp_async16(sst + soff, src);
        }
    };

    prefetch(0);
    CP_COMMIT();

    const int g  = lane >> 2;   // 0..7
    const int tg = lane & 3;    // 0..3

    for (int it = 0; it < KTILES; ++it) {
        if (it + 1 < KTILES) prefetch(it + 1);
        CP_COMMIT();
        CP_WAIT1();
        __syncthreads();

        const int s = it & 1;
        const float* Ah = sm + s * STAGE_FLOATS;
        const float* Al = Ah + PLANE;
        const float* Bh = Ah + 2 * PLANE;
        const float* Bl = Ah + 3 * PLANE;

        float acc[4][4][4];   // per-K-tile TC accumulator
#pragma unroll
        for (int i = 0; i < 4; i++)
#pragma unroll
            for (int j = 0; j < 4; j++)
#pragma unroll
                for (int q = 0; q < 4; q++) acc[i][j][q] = 0.f;

#pragma unroll
        for (int ks = 0; ks < 4; ++ks) {
            uint32_t ahi[4][4], alo[4][4], bhi[4][2], blo[4][2];
            const int c = ks * 8 + tg;
#pragma unroll
            for (int mi = 0; mi < 4; ++mi) {
                const int r = wm * 64 + mi * 16 + g;
                ahi[mi][0] = __float_as_uint(Ah[r * SA + c]);
                ahi[mi][1] = __float_as_uint(Ah[(r + 8) * SA + c]);
                ahi[mi][2] = __float_as_uint(Ah[r * SA + c + 4]);
                ahi[mi][3] = __float_as_uint(Ah[(r + 8) * SA + c + 4]);
                alo[mi][0] = __float_as_uint(Al[r * SA + c]);
                alo[mi][1] = __float_as_uint(Al[(r + 8) * SA + c]);
                alo[mi][2] = __float_as_uint(Al[r * SA + c + 4]);
                alo[mi][3] = __float_as_uint(Al[(r + 8) * SA + c + 4]);
            }
#pragma unroll
            for (int ni = 0; ni < 4; ++ni) {
                const int n = wn * 32 + ni * 8 + g;
                bhi[ni][0] = __float_as_uint(Bh[n * SA + c]);
                bhi[ni][1] = __float_as_uint(Bh[n * SA + c + 4]);
                blo[ni][0] = __float_as_uint(Bl[n * SA + c]);
                blo[ni][1] = __float_as_uint(Bl[n * SA + c + 4]);
            }
#pragma unroll
            for (int mi = 0; mi < 4; ++mi)
#pragma unroll
                for (int ni = 0; ni < 4; ++ni) {
                    mma8(acc[mi][ni], ahi[mi], bhi[ni]);
                    mma8(acc[mi][ni], ahi[mi], blo[ni]);
                    mma8(acc[mi][ni], alo[mi], bhi[ni]);
                }
        }

#pragma unroll
        for (int mi = 0; mi < 4; ++mi)
#pragma unroll
            for (int ni = 0; ni < 4; ++ni)
#pragma unroll
                for (int q = 0; q < 4; ++q)
                    sum[mi][ni][q] += acc[mi][ni][q];

        __syncthreads();
    }

    // ---- epilogue: sums -> SMEM cur tile [128 t][132], LIF scan + ballot ----
    float* cur = sm;   // 128*132*4 = 67584 <= 147456
#pragma unroll
    for (int mi = 0; mi < 4; ++mi)
#pragma unroll
        for (int ni = 0; ni < 4; ++ni) {
            const int r = wm * 64 + mi * 16 + g;
            const int c = wn * 32 + ni * 8 + tg * 2;
            cur[r * 132 + c]           = sum[mi][ni][0];
            cur[r * 132 + c + 1]       = sum[mi][ni][1];
            cur[(r + 8) * 132 + c]     = sum[mi][ni][2];
            cur[(r + 8) * 132 + c + 1] = sum[mi][ni][3];
        }
    __syncthreads();

    if (tid < 128) {                    // warps 0..3, all lanes active
        float mem1 = 0.f;
        uint32_t* dst = g_spkbits + (size_t)b * 128 * 32 + blockIdx.x * 4 + wid;
        float c = cur[tid];
#pragma unroll 4
        for (int t = 0; t < T_STEPS; ++t) {
            float cn = (t + 1 < T_STEPS) ? cur[(t + 1) * 132 + tid] : 0.f;
            const float reset = (mem1 > 1.0f) ? 1.0f : 0.0f;
            mem1 = 0.95f * mem1 + c - reset;
            const uint32_t word = __ballot_sync(0xffffffffu, mem1 > 1.0f);
            if (lane == 0) dst[(size_t)t * 32] = word;
            c = cn;
        }
    }
}

// ===================== K2: cur2 = spk @ W2^T from bitmask ==================
__global__ __launch_bounds__(256)
void snn_gemm2(const float* __restrict__ W2)   // [N_OUT, N_HID]
{
    __shared__ float w2s[N_HID * 11];
    const int tid  = threadIdx.x;
    const int wid  = tid >> 5;
    const int lane = tid & 31;

    for (int i = tid; i < N_HID * N_OUT; i += 256) {
        const int h = i / N_OUT;
        const int o = i - h * N_OUT;
        w2s[h * 11 + o] = W2[o * N_HID + h];
    }
    __syncthreads();

    const size_t m = (size_t)blockIdx.x * 8 + wid;
    uint32_t word = g_spkbits[m * 32 + lane];   // lane owns h in [lane*32, lane*32+32)

    float acc[N_OUT];
#pragma unroll
    for (int o = 0; o < N_OUT; o++) acc[o] = 0.f;

    while (word) {
        const int bit = __ffs(word) - 1;
        word &= word - 1;
        const float* w = w2s + (lane * 32 + bit) * 11;
#pragma unroll
        for (int o = 0; o < N_OUT; o++) acc[o] += w[o];
    }

#pragma unroll
    for (int o = 0; o < N_OUT; o++) {
        acc[o] += __shfl_down_sync(0xffffffffu, acc[o], 16);
        acc[o] += __shfl_down_sync(0xffffffffu, acc[o], 8);
        acc[o] += __shfl_down_sync(0xffffffffu, acc[o], 4);
        acc[o] += __shfl_down_sync(0xffffffffu, acc[o], 2);
        acc[o] += __shfl_down_sync(0xffffffffu, acc[o], 1);
    }
    if (lane == 0) {
#pragma unroll
        for (int o = 0; o < N_OUT; o++) g_cur2[m * N_OUT + o] = acc[o];
    }
}

// ===================== K3: mem2 leaky integration ==========================
__global__ void snn_scan2(float* __restrict__ out)   // [T, B, N_OUT]
{
    const int id = blockIdx.x * 256 + threadIdx.x;
    if (id >= BATCH * N_OUT) return;
    const int bb = id / N_OUT;
    const int o  = id - bb * N_OUT;

    float m2 = 0.f;
    for (int t = 0; t < T_STEPS; ++t) {
        m2 = 0.95f * m2 + g_cur2[((size_t)bb * T_STEPS + t) * N_OUT + o];
        out[((size_t)t * BATCH + bb) * N_OUT + o] = m2;
    }
}

// ===================== launch ==============================================
extern "C" void kernel_launch(void* const* d_in, const int* in_sizes, int n_in,
                              void* d_out, int out_size)
{
    const float* x  = (const float*)d_in[0];   // [B, T, K_IN]
    const float* W1 = (const float*)d_in[1];   // [N_HID, K_IN]
    const float* W2 = (const float*)d_in[2];   // [N_OUT, N_HID]
    float* out = (float*)d_out;                // [T, B, N_OUT]

    cudaFuncSetAttribute(snn_gemm_spike,
                         cudaFuncAttributeMaxDynamicSharedMemorySize, GEMM_SMEM);

    float* xs; float* ws;
    cudaGetSymbolAddress((void**)&xs, g_xs);
    cudaGetSymbolAddress((void**)&ws, g_ws);

    {   // planar split prepass
        const size_t nx = (size_t)M_TOTAL * (K_PAD / 4);
        const size_t nw = (size_t)N_HID * (K_PAD / 4);
        split_prepass<<<(unsigned)((nx + 255) / 256), 256>>>(
            x, xs, xs + (size_t)M_TOTAL * K_PAD, M_TOTAL);
        split_prepass<<<(unsigned)((nw + 255) / 256), 256>>>(
            W1, ws, ws + (size_t)N_HID * K_PAD, N_HID);
    }

    dim3 grid1(N_HID / 128, M_TOTAL / 128);    // (8, 256)
    snn_gemm_spike<<<grid1, 256, GEMM_SMEM>>>();
    snn_gemm2<<<M_TOTAL / 8, 256>>>(W2);
    snn_scan2<<<(BATCH * N_OUT + 255) / 256, 256>>>(out);
}